// round 16
// baseline (speedup 1.0000x reference)
#include <cuda_runtime.h>
#include <cuda_bf16.h>
#include <math.h>

// ---------------------------------------------------------------------------
// MessageBlock, round 16:
//   K0: fused zero + pipelined node MLP  (R15 version, 55.7us measured)
//   K1: edge kernel with INTRA-BLOCK role split: 256 threads,
//       warps 0-3 = dvec path (seg1+seg2), warps 4-7 = ds path (seg0).
//       Staging shared; per-warp per-edge slots 50 -> 36 (dvec wall).
// ---------------------------------------------------------------------------

#define F_DIM   128
#define PHI_DIM 384
#define RBF_D   20
#define TILE_M  32
#define KC      16
#define EB      64   // edges per block

typedef unsigned long long ull;

// scratch for per-node phi (15.7 MB), static device allocation (allowed)
__device__ float g_phi[10240 * PHI_DIM];

__device__ __forceinline__ float decode_rc(const int* p) {
    int v = *p;
    if (v > 0 && v < 1000000) return (float)v;   // int32 scalar
    return __uint_as_float((unsigned)v);          // float32 scalar bits
}

// ---- packed f32x2 helpers (sm_103a FFMA2 path) -----------------------------
__device__ __forceinline__ ull pk2(float lo, float hi) {
    ull r; asm("mov.b64 %0, {%1, %2};" : "=l"(r) : "f"(lo), "f"(hi)); return r;
}
__device__ __forceinline__ ull fma2(ull a, ull b, ull c) {
    ull d; asm("fma.rn.f32x2 %0, %1, %2, %3;" : "=l"(d) : "l"(a), "l"(b), "l"(c));
    return d;
}
__device__ __forceinline__ float2 unpk2(ull p) {
    float2 v; asm("mov.b64 {%0, %1}, %2;" : "=f"(v.x), "=f"(v.y) : "l"(p));
    return v;
}

// ---------------------------------------------------------------------------
// K0: fused zero + node MLP with pipelined weight staging (R15, unchanged).
// ---------------------------------------------------------------------------
__global__ void __launch_bounds__(256) node_mlp_kernel(
    const float* __restrict__ s,
    const float* __restrict__ Ws1, const float* __restrict__ bs1,
    const float* __restrict__ Ws2, const float* __restrict__ bs2,
    int n_nodes,
    float* __restrict__ outp, int out_n)
{
    __shared__ __align__(16) float sh_sm[TILE_M][F_DIM];        // s, then h
    __shared__ __align__(16) float w_sm[2][KC][F_DIM + 4];      // double buffer

    const int tid   = threadIdx.x;
    const int m_blk = blockIdx.x * TILE_M;
    const int n0 = (tid & 31) * 4;
    const int m0 = (tid >> 5) * 4;

    // fused zero of the poisoned output (grid-stride float4)
    {
        float4* o4 = (float4*)outp;
        const int n4 = out_n >> 2;
        const int gtid = blockIdx.x * 256 + tid;
        const int gsz  = gridDim.x * 256;
        for (int i = gtid; i < n4; i += gsz)
            o4[i] = make_float4(0.f, 0.f, 0.f, 0.f);
    }

    // stage s tile (zero-pad past n_nodes)
    for (int i = tid; i < TILE_M * 32; i += 256) {
        int m = i >> 5;
        float4 v = make_float4(0.f, 0.f, 0.f, 0.f);
        if (m_blk + m < n_nodes)
            v = ((const float4*)s)[(size_t)(m_blk + m) * 32 + (i & 31)];
        ((float4*)sh_sm)[i] = v;
    }

    const int kk0 = tid & 15;
    const int nn0 = tid >> 4;

    float wreg[8];
    #pragma unroll
    for (int j = 0; j < 8; j++)
        wreg[j] = __ldg(Ws1 + (nn0 + j * 16) * F_DIM + kk0);

    ull accp[4][2];
    #pragma unroll
    for (int i = 0; i < 4; i++) { accp[i][0] = 0ull; accp[i][1] = 0ull; }

    #pragma unroll 1
    for (int c = 0; c < 32; c++) {
        const int buf = c & 1;
        #pragma unroll
        for (int j = 0; j < 8; j++)
            w_sm[buf][kk0][nn0 + j * 16] = wreg[j];
        __syncthreads();

        if (c < 31) {
            const int cn = c + 1;
            const float* W;
            int kbase;
            if (cn < 8) { W = Ws1; kbase = cn * 16; }
            else {
                W = Ws2 + (size_t)((cn - 8) >> 3) * 128 * F_DIM;
                kbase = (cn & 7) * 16;
            }
            #pragma unroll
            for (int j = 0; j < 8; j++)
                wreg[j] = __ldg(W + (nn0 + j * 16) * F_DIM + kbase + kk0);
        }

        const int kc = (c & 7) * 16;
        #pragma unroll
        for (int k4 = 0; k4 < KC; k4 += 4) {
            float a[4][4];
            #pragma unroll
            for (int i = 0; i < 4; i++) {
                float4 t = *(const float4*)&sh_sm[m0 + i][kc + k4];
                a[i][0] = t.x; a[i][1] = t.y; a[i][2] = t.z; a[i][3] = t.w;
            }
            #pragma unroll
            for (int kk = 0; kk < 4; kk++) {
                double2 bq = *(const double2*)&w_sm[buf][k4 + kk][n0];
                ull bA = __double_as_longlong(bq.x);
                ull bB = __double_as_longlong(bq.y);
                #pragma unroll
                for (int i = 0; i < 4; i++) {
                    ull aa = pk2(a[i][kk], a[i][kk]);
                    accp[i][0] = fma2(aa, bA, accp[i][0]);
                    accp[i][1] = fma2(aa, bB, accp[i][1]);
                }
            }
        }

        if (c == 7) {
            __syncthreads();
            float bb[4];
            #pragma unroll
            for (int j = 0; j < 4; j++) bb[j] = bs1[n0 + j];
            #pragma unroll
            for (int i = 0; i < 4; i++) {
                float2 e0 = unpk2(accp[i][0]);
                float2 e1 = unpk2(accp[i][1]);
                float4 hv; float x;
                x = e0.x + bb[0]; hv.x = x / (1.f + __expf(-x));
                x = e0.y + bb[1]; hv.y = x / (1.f + __expf(-x));
                x = e1.x + bb[2]; hv.z = x / (1.f + __expf(-x));
                x = e1.y + bb[3]; hv.w = x / (1.f + __expf(-x));
                *(float4*)&sh_sm[m0 + i][n0] = hv;
                accp[i][0] = 0ull; accp[i][1] = 0ull;
            }
        } else if (c > 7 && (c & 7) == 7) {
            const int p = (c - 8) >> 3;
            float bb[4];
            #pragma unroll
            for (int j = 0; j < 4; j++) bb[j] = bs2[p * 128 + n0 + j];
            #pragma unroll
            for (int i = 0; i < 4; i++) {
                if (m_blk + m0 + i < n_nodes) {
                    float2 e0 = unpk2(accp[i][0]);
                    float2 e1 = unpk2(accp[i][1]);
                    float4 ov = make_float4(e0.x + bb[0], e0.y + bb[1],
                                            e1.x + bb[2], e1.y + bb[3]);
                    *(float4*)&g_phi[(size_t)(m_blk + m0 + i) * PHI_DIM + p * 128 + n0] = ov;
                }
                accp[i][0] = 0ull; accp[i][1] = 0ull;
            }
        }
    }
}

// ---------------------------------------------------------------------------
// K1: edge kernel, intra-block role split. 256 threads:
//   role 0 (warps 0-3): dvec path, channel ct, weights seg1+seg2 (40 regs)
//   role 1 (warps 4-7): ds path,  channel ct, weights seg0 (20 regs)
// Staging (rbf/geo/idx) shared, done once by all 256 threads.
// ---------------------------------------------------------------------------
__global__ void __launch_bounds__(256) edge_kernel(
    const float* __restrict__ vec,
    const float* __restrict__ edge_vector,
    const float* __restrict__ edge_distance,
    const float* __restrict__ edge_rbf,
    const float* __restrict__ Wrbf, const float* __restrict__ brbf,
    const int*   __restrict__ edge_idx,
    float* __restrict__ out_ds, float* __restrict__ out_dvec,
    int n_edges, const int* __restrict__ cutoff_ptr)
{
    __shared__ __align__(16) float rbf_sm[EB * RBF_D];   // 5 KB
    __shared__ float4 geo_sm[EB];                        // vn0,vn1,vn2,fcut
    __shared__ int2   idx_sm[EB];                        // (dst, src)

    const int tid  = threadIdx.x;
    const int ct   = tid & 127;        // channel
    const int role = tid >> 7;         // 0 = dvec, 1 = ds
    const float rc     = decode_rc(cutoff_ptr);
    const float inv_rc = 1.0f / rc;

    // role-specific weights
    ull wpA[RBF_D / 2], wpB[RBF_D / 2];
    float bA, bB;
    if (role == 0) {   // dvec: seg1 (wvv), seg2 (wvs)
        #pragma unroll
        for (int q = 0; q < RBF_D / 2; q++) {
            wpA[q] = pk2(Wrbf[(ct + 128) * RBF_D + 2 * q], Wrbf[(ct + 128) * RBF_D + 2 * q + 1]);
            wpB[q] = pk2(Wrbf[(ct + 256) * RBF_D + 2 * q], Wrbf[(ct + 256) * RBF_D + 2 * q + 1]);
        }
        bA = brbf[ct + 128];
        bB = brbf[ct + 256];
    } else {           // ds: seg0 (ws)
        #pragma unroll
        for (int q = 0; q < RBF_D / 2; q++) {
            wpA[q] = pk2(Wrbf[ct * RBF_D + 2 * q], Wrbf[ct * RBF_D + 2 * q + 1]);
            wpB[q] = 0ull;
        }
        bA = brbf[ct];
        bB = 0.f;
    }

    const int e0  = blockIdx.x * EB;
    const int cnt = min(EB, n_edges - e0);

    // stage per-edge metadata (256 threads)
    {
        const float4* src4 = (const float4*)(edge_rbf + (size_t)e0 * RBF_D);
        float4* dst4 = (float4*)rbf_sm;
        const int n4 = cnt * (RBF_D / 4);
        for (int i = tid; i < n4; i += 256) dst4[i] = src4[i];
    }
    if (tid < cnt) {
        const int e = e0 + tid;
        const float d = edge_distance[e];
        float fc = 0.5f * (cospif(d * inv_rc) + 1.0f);
        fc = (d < rc) ? fc : 0.0f;
        const float inv_d = 1.0f / d;
        geo_sm[tid] = make_float4(edge_vector[e * 3 + 0] * inv_d,
                                  edge_vector[e * 3 + 1] * inv_d,
                                  edge_vector[e * 3 + 2] * inv_d,
                                  fc);
        idx_sm[tid] = make_int2(edge_idx[e],              // dst (receiver)
                                edge_idx[n_edges + e]);   // src (sender)
    }
    __syncthreads();

    if (role == 0) {
        // -------- dvec path: 20 FMA2 + 5 LDG + 3 RED per edge --------
        #pragma unroll 1
        for (int el = 0; el < cnt; el++) {
            const int2   ii = idx_sm[el];
            const float4 g  = geo_sm[el];
            const int dst = ii.x, src = ii.y;

            const double2* fp = (const double2*)(rbf_sm + el * RBF_D);
            ull acc1 = 0ull, acc2 = 0ull;
            #pragma unroll
            for (int q = 0; q < 5; q++) {
                double2 f = fp[q];
                ull fA = __double_as_longlong(f.x);
                ull fB = __double_as_longlong(f.y);
                acc1 = fma2(fA, wpA[2 * q],     acc1);
                acc2 = fma2(fA, wpB[2 * q],     acc2);
                acc1 = fma2(fB, wpA[2 * q + 1], acc1);
                acc2 = fma2(fB, wpB[2 * q + 1], acc2);
            }
            float2 u1 = unpk2(acc1), u2 = unpk2(acc2);
            const float fc = g.w;
            const float a1 = (u1.x + u1.y + bA) * fc;
            const float a2 = (u2.x + u2.y + bB) * fc;

            const float* ph = g_phi + (size_t)src * PHI_DIM;
            const float wvv = __ldg(ph + 128 + ct) * a1;
            const float wvs = __ldg(ph + 256 + ct) * a2;

            const float* vp = vec + (size_t)src * PHI_DIM;
            float* op = out_dvec + (size_t)dst * PHI_DIM + ct;
            atomicAdd(op,       fmaf(wvv, __ldg(vp + ct      ), g.x * wvs));
            atomicAdd(op + 128, fmaf(wvv, __ldg(vp + ct + 128), g.y * wvs));
            atomicAdd(op + 256, fmaf(wvv, __ldg(vp + ct + 256), g.z * wvs));
        }
    } else {
        // -------- ds path: 10 FMA2 + 1 LDG + 1 RED per edge --------
        #pragma unroll 2
        for (int el = 0; el < cnt; el++) {
            const int2 ii = idx_sm[el];
            const float fc = geo_sm[el].w;

            const double2* fp = (const double2*)(rbf_sm + el * RBF_D);
            ull acc0 = 0ull;
            #pragma unroll
            for (int q = 0; q < 5; q++) {
                double2 f = fp[q];
                acc0 = fma2(__double_as_longlong(f.x), wpA[2 * q],     acc0);
                acc0 = fma2(__double_as_longlong(f.y), wpA[2 * q + 1], acc0);
            }
            float2 u0 = unpk2(acc0);
            const float a0 = (u0.x + u0.y + bA) * fc;

            const float ws = __ldg(g_phi + (size_t)ii.y * PHI_DIM + ct) * a0;
            atomicAdd(out_ds + (size_t)ii.x * F_DIM + ct, ws);
        }
    }
}

// ---------------------------------------------------------------------------
extern "C" void kernel_launch(void* const* d_in, const int* in_sizes, int n_in,
                              void* d_out, int out_size) {
    const float* s    = (const float*)d_in[0];
    const float* vec  = (const float*)d_in[1];
    const float* ev   = (const float*)d_in[2];
    const float* ed   = (const float*)d_in[3];
    const float* erbf = (const float*)d_in[4];
    const float* Ws1  = (const float*)d_in[5];
    const float* bs1  = (const float*)d_in[6];
    const float* Ws2  = (const float*)d_in[7];
    const float* bs2  = (const float*)d_in[8];
    const float* Wrbf = (const float*)d_in[9];
    const float* brbf = (const float*)d_in[10];
    const int*   eidx = (const int*)d_in[11];
    const int*   rcp  = (const int*)d_in[12];

    const int n_nodes = in_sizes[0] / F_DIM;
    const int n_edges = in_sizes[3];
    float* out_ds   = (float*)d_out;
    float* out_dvec = out_ds + (size_t)n_nodes * F_DIM;

    // K0: fused zero + pipelined per-node MLP -> g_phi
    node_mlp_kernel<<<(n_nodes + TILE_M - 1) / TILE_M, 256>>>(
        s, Ws1, bs1, Ws2, bs2, n_nodes, (float*)d_out, out_size);

    // K1: role-split edge kernel
    int nb = (n_edges + EB - 1) / EB;
    edge_kernel<<<nb, 256>>>(vec, ev, ed, erbf, Wrbf, brbf, eidx,
                             out_ds, out_dvec, n_edges, rcp);
}

// round 17
// speedup vs baseline: 1.0925x; 1.0925x over previous
#include <cuda_runtime.h>
#include <cuda_bf16.h>
#include <math.h>

// ---------------------------------------------------------------------------
// MessageBlock, round 17:
//   K0: fused zero + pipelined node MLP, TILE_M=64 via 2 m-subtiles per
//       thread (B-LDS wavefronts amortized 2x -> fma-bound). Dynamic smem.
//   K1: edge kernel, exact R2/R11/R14/R15 version (128.3us, stable).
// ---------------------------------------------------------------------------

#define F_DIM   128
#define PHI_DIM 384
#define RBF_D   20
#define TILE_M  64
#define KC      16
#define EB      64   // edges per block
#define WROW    (F_DIM + 4)   // w_sm row stride (16B-aligned)

typedef unsigned long long ull;

// scratch for per-node phi (15.7 MB), static device allocation (allowed)
__device__ float g_phi[10240 * PHI_DIM];

__device__ __forceinline__ float decode_rc(const int* p) {
    int v = *p;
    if (v > 0 && v < 1000000) return (float)v;   // int32 scalar
    return __uint_as_float((unsigned)v);          // float32 scalar bits
}

// ---- packed f32x2 helpers (sm_103a FFMA2 path) -----------------------------
__device__ __forceinline__ ull pk2(float lo, float hi) {
    ull r; asm("mov.b64 %0, {%1, %2};" : "=l"(r) : "f"(lo), "f"(hi)); return r;
}
__device__ __forceinline__ ull fma2(ull a, ull b, ull c) {
    ull d; asm("fma.rn.f32x2 %0, %1, %2, %3;" : "=l"(d) : "l"(a), "l"(b), "l"(c));
    return d;
}
__device__ __forceinline__ float2 unpk2(ull p) {
    float2 v; asm("mov.b64 {%0, %1}, %2;" : "=f"(v.x), "=f"(v.y) : "l"(p));
    return v;
}

// ---------------------------------------------------------------------------
// K0: fused zero + node MLP. TILE_M=64: thread owns m rows {m0..m0+3} and
// {m0+32..m0+35}, n cols {n0..n0+3}. A-loads warp-uniform (broadcast, 1 wf);
// B-loads serve both subtiles. Pipelined weight staging (R15).
// Dynamic smem: sh[64][128] (32KB) + w[2][16][132] (16.9KB) = 49.7KB.
// ---------------------------------------------------------------------------
__global__ void __launch_bounds__(256) node_mlp_kernel(
    const float* __restrict__ s,
    const float* __restrict__ Ws1, const float* __restrict__ bs1,
    const float* __restrict__ Ws2, const float* __restrict__ bs2,
    int n_nodes,
    float* __restrict__ outp, int out_n)
{
    extern __shared__ __align__(16) float dsm[];
    float (*sh_sm)[F_DIM] = (float(*)[F_DIM])dsm;                    // [64][128]
    float (*w_sm)[KC][WROW] = (float(*)[KC][WROW])(dsm + TILE_M * F_DIM);

    const int tid   = threadIdx.x;
    const int m_blk = blockIdx.x * TILE_M;
    const int n0 = (tid & 31) * 4;
    const int m0 = (tid >> 5) * 4;

    // fused zero of the poisoned output (grid-stride float4)
    {
        float4* o4 = (float4*)outp;
        const int n4 = out_n >> 2;
        const int gtid = blockIdx.x * 256 + tid;
        const int gsz  = gridDim.x * 256;
        for (int i = gtid; i < n4; i += gsz)
            o4[i] = make_float4(0.f, 0.f, 0.f, 0.f);
    }

    // stage s tile (zero-pad past n_nodes): 64 rows x 32 float4
    for (int i = tid; i < TILE_M * 32; i += 256) {
        int m = i >> 5;
        float4 v = make_float4(0.f, 0.f, 0.f, 0.f);
        if (m_blk + m < n_nodes)
            v = ((const float4*)s)[(size_t)(m_blk + m) * 32 + (i & 31)];
        ((float4*)sh_sm)[i] = v;
    }

    const int kk0 = tid & 15;
    const int nn0 = tid >> 4;

    float wreg[8];
    #pragma unroll
    for (int j = 0; j < 8; j++)
        wreg[j] = __ldg(Ws1 + (nn0 + j * 16) * F_DIM + kk0);

    ull accp[8][2];   // [subtile*4 + m-sub][n-pair]
    #pragma unroll
    for (int i = 0; i < 8; i++) { accp[i][0] = 0ull; accp[i][1] = 0ull; }

    #pragma unroll 1
    for (int c = 0; c < 32; c++) {
        const int buf = c & 1;
        #pragma unroll
        for (int j = 0; j < 8; j++)
            w_sm[buf][kk0][nn0 + j * 16] = wreg[j];
        __syncthreads();

        if (c < 31) {
            const int cn = c + 1;
            const float* W;
            int kbase;
            if (cn < 8) { W = Ws1; kbase = cn * 16; }
            else {
                W = Ws2 + (size_t)((cn - 8) >> 3) * 128 * F_DIM;
                kbase = (cn & 7) * 16;
            }
            #pragma unroll
            for (int j = 0; j < 8; j++)
                wreg[j] = __ldg(W + (nn0 + j * 16) * F_DIM + kbase + kk0);
        }

        const int kc = (c & 7) * 16;
        #pragma unroll
        for (int k4 = 0; k4 < KC; k4 += 4) {
            float a[8][4];
            #pragma unroll
            for (int ti = 0; ti < 2; ti++)
                #pragma unroll
                for (int i = 0; i < 4; i++) {
                    float4 t = *(const float4*)&sh_sm[ti * 32 + m0 + i][kc + k4];
                    a[ti * 4 + i][0] = t.x; a[ti * 4 + i][1] = t.y;
                    a[ti * 4 + i][2] = t.z; a[ti * 4 + i][3] = t.w;
                }
            #pragma unroll
            for (int kk = 0; kk < 4; kk++) {
                double2 bq = *(const double2*)&w_sm[buf][k4 + kk][n0];
                ull bA = __double_as_longlong(bq.x);
                ull bB = __double_as_longlong(bq.y);
                #pragma unroll
                for (int i = 0; i < 8; i++) {
                    ull aa = pk2(a[i][kk], a[i][kk]);
                    accp[i][0] = fma2(aa, bA, accp[i][0]);
                    accp[i][1] = fma2(aa, bB, accp[i][1]);
                }
            }
        }

        if (c == 7) {
            // stage 1 done: silu + bias -> h overwrites sh_sm
            __syncthreads();   // all warps finished reading s
            float bb[4];
            #pragma unroll
            for (int j = 0; j < 4; j++) bb[j] = bs1[n0 + j];
            #pragma unroll
            for (int ti = 0; ti < 2; ti++)
                #pragma unroll
                for (int i = 0; i < 4; i++) {
                    float2 e0 = unpk2(accp[ti * 4 + i][0]);
                    float2 e1 = unpk2(accp[ti * 4 + i][1]);
                    float4 hv; float x;
                    x = e0.x + bb[0]; hv.x = x / (1.f + __expf(-x));
                    x = e0.y + bb[1]; hv.y = x / (1.f + __expf(-x));
                    x = e1.x + bb[2]; hv.z = x / (1.f + __expf(-x));
                    x = e1.y + bb[3]; hv.w = x / (1.f + __expf(-x));
                    *(float4*)&sh_sm[ti * 32 + m0 + i][n0] = hv;
                    accp[ti * 4 + i][0] = 0ull; accp[ti * 4 + i][1] = 0ull;
                }
            // h visibility: covered by the sync at top of chunk 8
        } else if (c > 7 && (c & 7) == 7) {
            const int p = (c - 8) >> 3;
            float bb[4];
            #pragma unroll
            for (int j = 0; j < 4; j++) bb[j] = bs2[p * 128 + n0 + j];
            #pragma unroll
            for (int ti = 0; ti < 2; ti++)
                #pragma unroll
                for (int i = 0; i < 4; i++) {
                    const int m = m_blk + ti * 32 + m0 + i;
                    if (m < n_nodes) {
                        float2 e0 = unpk2(accp[ti * 4 + i][0]);
                        float2 e1 = unpk2(accp[ti * 4 + i][1]);
                        float4 ov = make_float4(e0.x + bb[0], e0.y + bb[1],
                                                e1.x + bb[2], e1.y + bb[3]);
                        *(float4*)&g_phi[(size_t)m * PHI_DIM + p * 128 + n0] = ov;
                    }
                    accp[ti * 4 + i][0] = 0ull; accp[ti * 4 + i][1] = 0ull;
                }
        }
    }
}

#define MLP_SMEM ((TILE_M * F_DIM + 2 * KC * WROW) * 4)

// ---------------------------------------------------------------------------
// K1: edge kernel — EXACT R2/R11/R14/R15 version (128.3us measured).
// 128 threads, thread t owns feature channels {t, t+128, t+256}.
// ---------------------------------------------------------------------------
__global__ void __launch_bounds__(128) edge_kernel(
    const float* __restrict__ vec,
    const float* __restrict__ edge_vector,
    const float* __restrict__ edge_distance,
    const float* __restrict__ edge_rbf,
    const float* __restrict__ Wrbf, const float* __restrict__ brbf,
    const int*   __restrict__ edge_idx,
    float* __restrict__ out_ds, float* __restrict__ out_dvec,
    int n_edges, const int* __restrict__ cutoff_ptr)
{
    __shared__ __align__(16) float rbf_sm[EB * RBF_D];   // 5 KB
    __shared__ float4 geo_sm[EB];                        // vn0,vn1,vn2,fcut
    __shared__ int2   idx_sm[EB];                        // (dst, src)

    const int tid = threadIdx.x;
    const float rc     = decode_rc(cutoff_ptr);
    const float inv_rc = 1.0f / rc;

    ull wp0[RBF_D / 2], wp1[RBF_D / 2], wp2[RBF_D / 2];
    #pragma unroll
    for (int q = 0; q < RBF_D / 2; q++) {
        wp0[q] = pk2(Wrbf[(tid      ) * RBF_D + 2 * q], Wrbf[(tid      ) * RBF_D + 2 * q + 1]);
        wp1[q] = pk2(Wrbf[(tid + 128) * RBF_D + 2 * q], Wrbf[(tid + 128) * RBF_D + 2 * q + 1]);
        wp2[q] = pk2(Wrbf[(tid + 256) * RBF_D + 2 * q], Wrbf[(tid + 256) * RBF_D + 2 * q + 1]);
    }
    const float b0 = brbf[tid], b1 = brbf[tid + 128], b2 = brbf[tid + 256];

    const int n_batches = (n_edges + EB - 1) / EB;
    for (int batch = blockIdx.x; batch < n_batches; batch += gridDim.x) {
        const int e0  = batch * EB;
        const int cnt = min(EB, n_edges - e0);

        __syncthreads();
        {
            const float4* src4 = (const float4*)(edge_rbf + (size_t)e0 * RBF_D);
            float4* dst4 = (float4*)rbf_sm;
            const int n4 = cnt * (RBF_D / 4);
            for (int i = tid; i < n4; i += 128) dst4[i] = src4[i];
        }
        if (tid < cnt) {
            const int e = e0 + tid;
            const float d = edge_distance[e];
            float fc = 0.5f * (cospif(d * inv_rc) + 1.0f);
            fc = (d < rc) ? fc : 0.0f;
            const float inv_d = 1.0f / d;
            geo_sm[tid] = make_float4(edge_vector[e * 3 + 0] * inv_d,
                                      edge_vector[e * 3 + 1] * inv_d,
                                      edge_vector[e * 3 + 2] * inv_d,
                                      fc);
            idx_sm[tid] = make_int2(edge_idx[e],              // dst (receiver)
                                    edge_idx[n_edges + e]);   // src (sender)
        }
        __syncthreads();

        #pragma unroll 1
        for (int el = 0; el < cnt; el++) {
            const int2  ii = idx_sm[el];
            const float4 g = geo_sm[el];
            const int dst = ii.x, src = ii.y;

            const double2* fp = (const double2*)(rbf_sm + el * RBF_D);
            ull acc0 = 0ull, acc1 = 0ull, acc2 = 0ull;
            #pragma unroll
            for (int q = 0; q < 5; q++) {
                double2 f = fp[q];
                ull fA = __double_as_longlong(f.x);
                ull fB = __double_as_longlong(f.y);
                acc0 = fma2(fA, wp0[2 * q], acc0);
                acc1 = fma2(fA, wp1[2 * q], acc1);
                acc2 = fma2(fA, wp2[2 * q], acc2);
                acc0 = fma2(fB, wp0[2 * q + 1], acc0);
                acc1 = fma2(fB, wp1[2 * q + 1], acc1);
                acc2 = fma2(fB, wp2[2 * q + 1], acc2);
            }
            float2 u0 = unpk2(acc0), u1 = unpk2(acc1), u2 = unpk2(acc2);
            const float fc = g.w;
            const float a0 = (u0.x + u0.y + b0) * fc;
            const float a1 = (u1.x + u1.y + b1) * fc;
            const float a2 = (u2.x + u2.y + b2) * fc;

            const float* ph = g_phi + (size_t)src * PHI_DIM;
            const float ws  = __ldg(ph + tid)       * a0;
            const float wvv = __ldg(ph + tid + 128) * a1;
            const float wvs = __ldg(ph + tid + 256) * a2;

            atomicAdd(out_ds + (size_t)dst * F_DIM + tid, ws);

            const float* vp = vec + (size_t)src * PHI_DIM;
            float* op = out_dvec + (size_t)dst * PHI_DIM + tid;
            atomicAdd(op,       fmaf(wvv, __ldg(vp + tid      ), g.x * wvs));
            atomicAdd(op + 128, fmaf(wvv, __ldg(vp + tid + 128), g.y * wvs));
            atomicAdd(op + 256, fmaf(wvv, __ldg(vp + tid + 256), g.z * wvs));
        }
    }
}

// ---------------------------------------------------------------------------
extern "C" void kernel_launch(void* const* d_in, const int* in_sizes, int n_in,
                              void* d_out, int out_size) {
    const float* s    = (const float*)d_in[0];
    const float* vec  = (const float*)d_in[1];
    const float* ev   = (const float*)d_in[2];
    const float* ed   = (const float*)d_in[3];
    const float* erbf = (const float*)d_in[4];
    const float* Ws1  = (const float*)d_in[5];
    const float* bs1  = (const float*)d_in[6];
    const float* Ws2  = (const float*)d_in[7];
    const float* bs2  = (const float*)d_in[8];
    const float* Wrbf = (const float*)d_in[9];
    const float* brbf = (const float*)d_in[10];
    const int*   eidx = (const int*)d_in[11];
    const int*   rcp  = (const int*)d_in[12];

    const int n_nodes = in_sizes[0] / F_DIM;
    const int n_edges = in_sizes[3];
    float* out_ds   = (float*)d_out;
    float* out_dvec = out_ds + (size_t)n_nodes * F_DIM;

    // K0: fused zero + pipelined per-node MLP (TILE_M=64) -> g_phi
    cudaFuncSetAttribute(node_mlp_kernel,
                         cudaFuncAttributeMaxDynamicSharedMemorySize, MLP_SMEM);
    node_mlp_kernel<<<(n_nodes + TILE_M - 1) / TILE_M, 256, MLP_SMEM>>>(
        s, Ws1, bs1, Ws2, bs2, n_nodes, (float*)d_out, out_size);

    // K1: per-edge filter + scatter (exact R2 version)
    int nb = (n_edges + EB - 1) / EB;
    edge_kernel<<<nb, 128>>>(vec, ev, ed, erbf, Wrbf, brbf, eidx,
                             out_ds, out_dvec, n_edges, rcp);
}